// round 8
// baseline (speedup 1.0000x reference)
#include <cuda_runtime.h>

// Gaussian-splat over-compositing, N pixels x K gaussians, sm_103a.
// R8: tile-sorted pixels (atomic-free counting sort, transposed partials) +
// per-BLOCK compacted active-gaussian list (dense unrollable mainloop) +
// exact skip semantics (u *= g^m catch-up via ex2/lg2).

#define MAXK   128
#define MAXN   (1 << 18)
#define TILE_W 32
#define TXD    16
#define NT     (TXD * TXD)       // 256 tiles
#define Q_CUT  15.0f             // skip if q upper bound < -Q_CUT
#define PA_FB  1e-4f             // fallback threshold on final alpha
#define NSB    128               // max sort blocks
#define SPT    8                 // pixels per sort thread (256 thr -> 2048/blk)

typedef unsigned long long u64;
typedef unsigned int u32;

// ---- device scratch (static, no allocation) ----
__device__ int d_part[NT][NSB];  // per-(tile,block) counts -> bases (transposed)
__device__ int d_order[MAXN];
__device__ u32 d_tmask[NT][4];

// ---- packed f32x2 helpers ----
__device__ __forceinline__ u64 pack2(float a, float b) {
    u64 r; asm("mov.b64 %0, {%1, %2};" : "=l"(r) : "f"(a), "f"(b)); return r;
}
__device__ __forceinline__ void unpack2(u64 v, float& a, float& b) {
    asm("mov.b64 {%0, %1}, %2;" : "=f"(a), "=f"(b) : "l"(v));
}
__device__ __forceinline__ u64 fma2(u64 a, u64 b, u64 c) {
    u64 d; asm("fma.rn.f32x2 %0, %1, %2, %3;" : "=l"(d) : "l"(a), "l"(b), "l"(c)); return d;
}
__device__ __forceinline__ u64 add2(u64 a, u64 b) {
    u64 d; asm("add.rn.f32x2 %0, %1, %2;" : "=l"(d) : "l"(a), "l"(b)); return d;
}
__device__ __forceinline__ u64 mul2(u64 a, u64 b) {
    u64 d; asm("mul.rn.f32x2 %0, %1, %2;" : "=l"(d) : "l"(a), "l"(b)); return d;
}
__device__ __forceinline__ float ex2f_(float x) {
    float y; asm("ex2.approx.f32 %0, %1;" : "=f"(y) : "f"(x)); return y;
}
__device__ __forceinline__ float rcpf_(float x) {
    float y; asm("rcp.approx.f32 %0, %1;" : "=f"(y) : "f"(x)); return y;
}
__device__ __forceinline__ float lg2f_(float x) {
    float y; asm("lg2.approx.f32 %0, %1;" : "=f"(y) : "f"(x)); return y;
}

__device__ __forceinline__ int tile_of(float x, float y) {
    int tx = (int)(x * (1.0f / TILE_W)); tx = min(max(tx, 0), TXD - 1);
    int ty = (int)(y * (1.0f / TILE_W)); ty = min(max(ty, 0), TXD - 1);
    return ty * TXD + tx;
}

// ---- pair state: 2 pixels packed in f32x2 lanes ----
struct PairState {
    u64 x, y, x2, xy, y2;   // centered coords + monomials
    u64 u0, u1, u2;         // scaled color numerators
    u64 pa, omp, g;         // alpha, 1-alpha, carry factor pa/(pa+eps)
};

__device__ __forceinline__ void pair_init(PairState& S, float2 P0, float2 P1) {
    float ax = P0.x - 256.0f, ay = P0.y - 256.0f;
    float bx = P1.x - 256.0f, by = P1.y - 256.0f;
    S.x  = pack2(ax, bx);
    S.y  = pack2(ay, by);
    S.x2 = mul2(S.x, S.x);
    S.xy = mul2(S.x, S.y);
    S.y2 = mul2(S.y, S.y);
    S.u0 = S.u1 = S.u2 = 0ull;
    S.pa = 0ull; S.g = 0ull;
    S.omp = pack2(1.0f, 1.0f);
}

__device__ __forceinline__ void pair_step(PairState& S,
                                          ulonglong2 g0, ulonglong2 g1,
                                          ulonglong2 g2, ulonglong2 g3,
                                          ulonglong2 g4,
                                          u64 EPS2, u64 NEG1) {
    u64 t = fma2(g2.x, S.y, g2.y);       // Ey*y + F
    t = fma2(g1.y, S.x, t);              // + Dx*x
    t = fma2(g1.x, S.y2, t);             // + C*y2
    t = fma2(g0.y, S.xy, t);             // + B2*xy
    u64 q = fma2(g0.x, S.x2, t);         // + A*x2

    float qa, qb; unpack2(q, qa, qb);
    u64 e = pack2(ex2f_(qa), ex2f_(qb)); // alpha_k * gaussian

    u64 w = mul2(e, S.omp);
    S.u0 = fma2(S.u0, S.g, mul2(g3.x, w));   // u = u*g_prev + col*w
    S.u1 = fma2(S.u1, S.g, mul2(g3.y, w));
    S.u2 = fma2(S.u2, S.g, mul2(g4.x, w));

    u64 pan = add2(S.pa, w);
    S.omp = fma2(w, NEG1, S.omp);
    u64 d = add2(pan, EPS2);
    float da, db; unpack2(d, da, db);
    u64 r = pack2(rcpf_(da), rcpf_(db));
    S.g = mul2(pan, r);
    S.pa = pan;
}

// apply m skipped steps: u *= g^m (pa unchanged during skips)
__device__ __forceinline__ void pair_catchup(PairState& S, float fm) {
    float g0, g1; unpack2(S.g, g0, g1);
    float gm0 = ex2f_(fm * lg2f_(g0));   // g==1 -> 1; g==0 -> 0
    float gm1 = ex2f_(fm * lg2f_(g1));
    u64 gm = pack2(gm0, gm1);
    S.u0 = mul2(S.u0, gm);
    S.u1 = mul2(S.u1, gm);
    S.u2 = mul2(S.u2, gm);
}

// ---- shared param prep (identical math to R3, which passed) ----
__device__ __forceinline__ void prep_params(float2* sp,
                                            const float* mu, const float* alpha,
                                            const float* color, const float* scales,
                                            const float* thetas, int K) {
    const float L2E = 1.44269504088896340736f;
    for (int k = threadIdx.x; k < K; k += blockDim.x) {
        float th = thetas[k];
        float c = cosf(th), s = sinf(th);
        float sx = fmaxf(scales[2 * k + 0], 0.1f);
        float sy = fmaxf(scales[2 * k + 1], 0.1f);
        float ix = 1.0f / (sx * sx);
        float iy = 1.0f / (sy * sy);
        float S00 = c * c * ix + s * s * iy;
        float S01 = c * s * (ix - iy);
        float S11 = s * s * ix + c * c * iy;
        float h = -0.5f * L2E;
        float A  = h * S00;
        float B2 = (2.0f * h) * S01;
        float C  = h * S11;
        float a  = fminf(fmaxf(alpha[k], 0.0f), 1.0f);
        float la = log2f(fmaxf(a, 1e-38f));
        float c0 = fminf(fmaxf(color[3 * k + 0], 0.0f), 255.0f);
        float c1 = fminf(fmaxf(color[3 * k + 1], 0.0f), 255.0f);
        float c2 = fminf(fmaxf(color[3 * k + 2], 0.0f), 255.0f);
        float mx = mu[2 * k + 0] - 256.0f;
        float my = mu[2 * k + 1] - 256.0f;
        float Dx = -(2.0f * A * mx + B2 * my);
        float Ey = -(B2 * mx + 2.0f * C * my);
        float F  = (A * mx * mx + B2 * mx * my + C * my * my) + la;
        float2* p = &sp[k * 10];
        p[0] = make_float2(A, A);   p[1] = make_float2(B2, B2);
        p[2] = make_float2(C, C);   p[3] = make_float2(Dx, Dx);
        p[4] = make_float2(Ey, Ey); p[5] = make_float2(F, F);
        p[6] = make_float2(c0, c0); p[7] = make_float2(c1, c1);
        p[8] = make_float2(c2, c2); p[9] = make_float2(0.0f, 0.0f);
    }
}

// ============================ binning kernels ============================

// blocks [0,hb): per-block tile histogram -> d_part[t][blk]
// blocks [hb,hb+4): per-(tile,k-word) activity mask
__global__ __launch_bounds__(256)
void k_histmask(const float2* __restrict__ pos2, int n, int hb,
                const float* __restrict__ mu,
                const float* __restrict__ alpha,
                const float* __restrict__ scales, int K) {
    int tid = threadIdx.x;
    if (blockIdx.x >= (u32)hb) {
        // ---- mask part ----
        int id = (blockIdx.x - hb) * 256 + tid;   // tile*4 + word
        if (id >= NT * 4) return;
        int tile = id >> 2, word = id & 3;
        int ty = tile / TXD, tx = tile % TXD;
        float rx0 = tx * (float)TILE_W, rx1 = rx0 + TILE_W;
        float ry0 = ty * (float)TILE_W, ry1 = ry0 + TILE_W;
        u32 bits = 0;
        for (int j = 0; j < 32; j++) {
            int k = word * 32 + j;
            if (k >= K) break;
            float mx = mu[2 * k + 0], my = mu[2 * k + 1];
            float dx = fmaxf(0.0f, fmaxf(rx0 - mx, mx - rx1));
            float dy = fmaxf(0.0f, fmaxf(ry0 - my, my - ry1));
            float d2 = dx * dx + dy * dy;
            float a  = fminf(fmaxf(alpha[k], 0.0f), 1.0f);
            float la = log2f(fmaxf(a, 1e-38f));
            float sx = fmaxf(scales[2 * k + 0], 0.1f);
            float sy = fmaxf(scales[2 * k + 1], 0.1f);
            float sm = fmaxf(sx, sy);
            float rhs = (Q_CUT + la) * sm * sm;
            if (d2 * 0.72134752f < rhs) bits |= (1u << j);
        }
        d_tmask[tile][word] = bits;
        return;
    }
    // ---- hist part ----
    __shared__ int sh[NT];
    sh[tid] = 0;
    __syncthreads();
    int base = blockIdx.x * (256 * SPT);
#pragma unroll
    for (int j = 0; j < SPT; j++) {
        int i = base + j * 256 + tid;
        if (i < n) {
            float2 p = pos2[i];
            atomicAdd(&sh[tile_of(p.x, p.y)], 1);
        }
    }
    __syncthreads();
    d_part[tid][blockIdx.x] = sh[tid];
}

// single block: per-thread contiguous row walk (transposed layout)
__global__ __launch_bounds__(256) void k_offsets(int nblocks) {
    __shared__ int s[NT];
    int t = threadIdx.x;     // one thread per tile, row d_part[t][*] contiguous
    int total = 0;
#pragma unroll 8
    for (int b = 0; b < nblocks; b++) total += d_part[t][b];
    s[t] = total;
    __syncthreads();
    int v0 = total;
    for (int off = 1; off < NT; off <<= 1) {
        int v = (t >= off) ? s[t - off] : 0;
        __syncthreads();
        s[t] += v;
        __syncthreads();
    }
    int run = s[t] - v0;     // tile base
#pragma unroll 8
    for (int b = 0; b < nblocks; b++) {
        int c = d_part[t][b];
        d_part[t][b] = run;
        run += c;
    }
}

// scatter: rank via smem atomics only, base from transposed d_part
__global__ __launch_bounds__(256) void k_scatter(const float2* __restrict__ pos2, int n) {
    __shared__ int sh[NT];
    __shared__ int sbase[NT];
    int tid = threadIdx.x;
    sh[tid] = 0;
    sbase[tid] = d_part[tid][blockIdx.x];
    __syncthreads();
    int base = blockIdx.x * (256 * SPT);
#pragma unroll
    for (int j = 0; j < SPT; j++) {
        int i = base + j * 256 + tid;
        if (i < n) {
            float2 p = pos2[i];
            int t = tile_of(p.x, p.y);
            int r = atomicAdd(&sh[t], 1);
            d_order[sbase[t] + r] = i;
        }
    }
}

// ============================ main kernel ============================

__global__ __launch_bounds__(128)
void k_main(const float* __restrict__ pos,
            const float* __restrict__ mu,
            const float* __restrict__ alpha,
            const float* __restrict__ color,
            const float* __restrict__ scales,
            const float* __restrict__ thetas,
            float4* __restrict__ out,
            int n, int K)
{
    __shared__ __align__(16) float2 sp[MAXK * 10];
    __shared__ int   skidx[MAXK];
    __shared__ float sfgap[MAXK];
    __shared__ u32   uwords[4];
    __shared__ int   wcnt[4], wbase[4], snact;

    prep_params(sp, mu, alpha, color, scales, thetas, K);

    // chunk permutation to spread hot tiles across SMs
    u32 g = gridDim.x;
    u32 mult = (g % 331u == 0u) ? 1u : 331u;
    u32 chunk = (blockIdx.x * mult) % g;

    int tid = threadIdx.x;
    int start = (int)chunk * 512;                    // block pixel range
    int endi  = min(start + 512, n) - 1;

    // block tile range (sorted order -> contiguous tile ids)
    if (tid < 4) {
        const float2* pos2 = (const float2*)pos;
        int iF = d_order[start];
        int iL = d_order[max(endi, start)];
        float2 pF = pos2[iF];
        float2 pL = pos2[iL];
        int tF = tile_of(pF.x, pF.y);
        int tL = tile_of(pL.x, pL.y);
        u32 bits = 0;
        for (int t = tF; t <= tL; t++) bits |= d_tmask[t][tid];
        uwords[tid] = bits;
    }
    __syncthreads();

    // compact active-k list (blockDim=128, K<=128)
    int lane = tid & 31, wid = tid >> 5;
    bool act = (tid < K) && ((uwords[tid >> 5] >> (tid & 31)) & 1u);
    u32 bal = __ballot_sync(0xffffffffu, act);
    if (lane == 0) wcnt[wid] = __popc(bal);
    __syncthreads();
    if (tid == 0) {
        int r = 0;
        for (int w = 0; w < 4; w++) { wbase[w] = r; r += wcnt[w]; }
        snact = r;
    }
    __syncthreads();
    if (act) {
        int pos_ = wbase[wid] + __popc(bal & ((1u << lane) - 1u));
        skidx[pos_] = tid;
    }
    __syncthreads();
    int nact = snact;
    if (tid < nact) {
        int kk = skidx[tid];
        int pk = tid ? skidx[tid - 1] : -1;
        sfgap[tid] = (float)(kk - pk - 1);
    }
    __syncthreads();

    // 2 pairs (4 pixels) per thread
    int pA = (start >> 1) + tid;
    int pB = pA + 128;
    int iA0 = pA * 2, iA1 = iA0 + 1, iB0 = pB * 2, iB1 = iB0 + 1;
    bool vA0 = (iA0 < n), vA1 = (iA1 < n), vB0 = (iB0 < n), vB1 = (iB1 < n);

    int idxA0 = 0, idxA1 = 0, idxB0 = 0, idxB1 = 0;
    if (vA1)      { int2 o = ((const int2*)d_order)[pA]; idxA0 = o.x; idxA1 = o.y; }
    else if (vA0) { idxA0 = d_order[iA0]; }
    if (vB1)      { int2 o = ((const int2*)d_order)[pB]; idxB0 = o.x; idxB1 = o.y; }
    else if (vB0) { idxB0 = d_order[iB0]; }

    const float2* pos2 = (const float2*)pos;
    float2 PA0 = vA0 ? pos2[idxA0] : make_float2(0.0f, 0.0f);
    float2 PA1 = vA1 ? pos2[idxA1] : make_float2(0.0f, 0.0f);
    float2 PB0 = vB0 ? pos2[idxB0] : make_float2(0.0f, 0.0f);
    float2 PB1 = vB1 ? pos2[idxB1] : make_float2(0.0f, 0.0f);

    PairState Spa, Spb;
    pair_init(Spa, PA0, PA1);
    pair_init(Spb, PB0, PB1);

    const u64 EPS2 = pack2(1e-8f, 1e-8f);
    const u64 NEG1 = pack2(-1.0f, -1.0f);
    const ulonglong2* __restrict__ gp = (const ulonglong2*)sp;

#pragma unroll 2
    for (int i = 0; i < nact; i++) {
        float fm = sfgap[i];
        int k = skidx[i];
        if (fm > 0.0f) {                 // block-uniform branch
            pair_catchup(Spa, fm);
            pair_catchup(Spb, fm);
        }
        ulonglong2 g0 = gp[k * 5 + 0];
        ulonglong2 g1 = gp[k * 5 + 1];
        ulonglong2 g2 = gp[k * 5 + 2];
        ulonglong2 g3 = gp[k * 5 + 3];
        ulonglong2 g4 = gp[k * 5 + 4];
        pair_step(Spa, g0, g1, g2, g3, g4, EPS2, NEG1);
        pair_step(Spb, g0, g1, g2, g3, g4, EPS2, NEG1);
    }
    if (nact > 0) {
        float ft = (float)(K - 1 - skidx[nact - 1]);
        if (ft > 0.0f) {
            pair_catchup(Spa, ft);
            pair_catchup(Spb, ft);
        }
    }

    float paA0, paA1; unpack2(Spa.pa, paA0, paA1);
    float paB0, paB1; unpack2(Spb.pa, paB0, paB1);

    // fallback: exact full loop for low-alpha pixels (rare, warp-coherent)
    bool needA = (vA0 && paA0 < PA_FB) || (vA1 && paA1 < PA_FB);
    bool needB = (vB0 && paB0 < PA_FB) || (vB1 && paB1 < PA_FB);
    if (__any_sync(0xffffffffu, needA)) {
        PairState F;
        pair_init(F, PA0, PA1);
        for (int k = 0; k < K; k++)
            pair_step(F, gp[k*5+0], gp[k*5+1], gp[k*5+2], gp[k*5+3], gp[k*5+4],
                      EPS2, NEG1);
        if (needA) { Spa = F; unpack2(Spa.pa, paA0, paA1); }
    }
    if (__any_sync(0xffffffffu, needB)) {
        PairState F;
        pair_init(F, PB0, PB1);
        for (int k = 0; k < K; k++)
            pair_step(F, gp[k*5+0], gp[k*5+1], gp[k*5+2], gp[k*5+3], gp[k*5+4],
                      EPS2, NEG1);
        if (needB) { Spb = F; unpack2(Spb.pa, paB0, paB1); }
    }

    float u00, u01, u10, u11, u20, u21;

    unpack2(Spa.u0, u00, u01); unpack2(Spa.u1, u10, u11); unpack2(Spa.u2, u20, u21);
    if (vA0) {
        float r = rcpf_(paA0 + 1e-8f);
        out[idxA0] = make_float4(fminf(fmaxf(u00 * r, 0.0f), 255.0f),
                                 fminf(fmaxf(u10 * r, 0.0f), 255.0f),
                                 fminf(fmaxf(u20 * r, 0.0f), 255.0f),
                                 fminf(fmaxf(paA0, 0.0f), 1.0f) * 255.0f);
    }
    if (vA1) {
        float r = rcpf_(paA1 + 1e-8f);
        out[idxA1] = make_float4(fminf(fmaxf(u01 * r, 0.0f), 255.0f),
                                 fminf(fmaxf(u11 * r, 0.0f), 255.0f),
                                 fminf(fmaxf(u21 * r, 0.0f), 255.0f),
                                 fminf(fmaxf(paA1, 0.0f), 1.0f) * 255.0f);
    }
    unpack2(Spb.u0, u00, u01); unpack2(Spb.u1, u10, u11); unpack2(Spb.u2, u20, u21);
    if (vB0) {
        float r = rcpf_(paB0 + 1e-8f);
        out[idxB0] = make_float4(fminf(fmaxf(u00 * r, 0.0f), 255.0f),
                                 fminf(fmaxf(u10 * r, 0.0f), 255.0f),
                                 fminf(fmaxf(u20 * r, 0.0f), 255.0f),
                                 fminf(fmaxf(paB0, 0.0f), 1.0f) * 255.0f);
    }
    if (vB1) {
        float r = rcpf_(paB1 + 1e-8f);
        out[idxB1] = make_float4(fminf(fmaxf(u01 * r, 0.0f), 255.0f),
                                 fminf(fmaxf(u11 * r, 0.0f), 255.0f),
                                 fminf(fmaxf(u21 * r, 0.0f), 255.0f),
                                 fminf(fmaxf(paB1, 0.0f), 1.0f) * 255.0f);
    }
}

// ---- plain full-loop kernel (fallback path for unexpected shapes) ----
__global__ __launch_bounds__(128)
void k_plain(const float* __restrict__ pos,
             const float* __restrict__ mu,
             const float* __restrict__ alpha,
             const float* __restrict__ color,
             const float* __restrict__ scales,
             const float* __restrict__ thetas,
             float4* __restrict__ out,
             int n, int K)
{
    __shared__ __align__(16) float2 sp[MAXK * 10];
    prep_params(sp, mu, alpha, color, scales, thetas, K);
    __syncthreads();

    int pairIdx = blockIdx.x * blockDim.x + threadIdx.x;
    int i0 = pairIdx * 2, i1 = i0 + 1;
    bool v0 = (i0 < n), v1 = (i1 < n);
    const float2* pos2 = (const float2*)pos;
    float2 P0 = v0 ? pos2[i0] : make_float2(0.0f, 0.0f);
    float2 P1 = v1 ? pos2[i1] : make_float2(0.0f, 0.0f);

    PairState S;
    pair_init(S, P0, P1);
    const u64 EPS2 = pack2(1e-8f, 1e-8f);
    const u64 NEG1 = pack2(-1.0f, -1.0f);
    const ulonglong2* __restrict__ gp = (const ulonglong2*)sp;
    for (int k = 0; k < K; k++)
        pair_step(S, gp[k*5+0], gp[k*5+1], gp[k*5+2], gp[k*5+3], gp[k*5+4],
                  EPS2, NEG1);

    float pa0, pa1; unpack2(S.pa, pa0, pa1);
    float u00, u01; unpack2(S.u0, u00, u01);
    float u10, u11; unpack2(S.u1, u10, u11);
    float u20, u21; unpack2(S.u2, u20, u21);
    if (v0) {
        float r = rcpf_(pa0 + 1e-8f);
        out[i0] = make_float4(fminf(fmaxf(u00 * r, 0.0f), 255.0f),
                              fminf(fmaxf(u10 * r, 0.0f), 255.0f),
                              fminf(fmaxf(u20 * r, 0.0f), 255.0f),
                              fminf(fmaxf(pa0, 0.0f), 1.0f) * 255.0f);
    }
    if (v1) {
        float r = rcpf_(pa1 + 1e-8f);
        out[i1] = make_float4(fminf(fmaxf(u01 * r, 0.0f), 255.0f),
                              fminf(fmaxf(u11 * r, 0.0f), 255.0f),
                              fminf(fmaxf(u21 * r, 0.0f), 255.0f),
                              fminf(fmaxf(pa1, 0.0f), 1.0f) * 255.0f);
    }
}

extern "C" void kernel_launch(void* const* d_in, const int* in_sizes, int n_in,
                              void* d_out, int out_size)
{
    const float* pos    = (const float*)d_in[0];
    const float* mu     = (const float*)d_in[1];
    const float* alpha  = (const float*)d_in[2];
    const float* color  = (const float*)d_in[3];
    const float* scales = (const float*)d_in[4];
    const float* thetas = (const float*)d_in[5];

    int n = in_sizes[0] / 2;     // pixels
    int K = in_sizes[2];         // gaussians

    if (n > MAXN || K > MAXK || n < 1) {
        int Kc = K > MAXK ? MAXK : K;
        int pairs = (n + 1) / 2;
        int grid = (pairs + 127) / 128;
        k_plain<<<grid, 128>>>(pos, mu, alpha, color, scales, thetas,
                               (float4*)d_out, n, Kc);
        return;
    }

    int mainGrid = (n + 511) / 512;              // 512 pixels per block
    int sb = (n + 256 * SPT - 1) / (256 * SPT);  // <= NSB
    if (sb > NSB) sb = NSB;

    k_histmask<<<sb + 4, 256>>>((const float2*)pos, n, sb, mu, alpha, scales, K);
    k_offsets<<<1, 256>>>(sb);
    k_scatter<<<sb, 256>>>((const float2*)pos, n);
    k_main<<<mainGrid, 128>>>(pos, mu, alpha, color, scales, thetas,
                              (float4*)d_out, n, K);
}

// round 9
// speedup vs baseline: 3.1316x; 3.1316x over previous
#include <cuda_runtime.h>

// Gaussian-splat over-compositing, N pixels x K gaussians, sm_103a.
// R9: dense exact loop (R3 math, passed @2.5e-6), re-shaped for wave balance:
// 64-thread blocks, 4 px/thread (2 packed f32x2 pair-states), grid ~7/SM,
// unroll 8.
//   e   = exp2(A*x2 + B2*xy + C*y2 + Dx*x + Ey*y + F)
//   w   = e * omp;  u_c = u_c * g_prev + col_c * w
//   pan = pa + w;  omp -= w;  r = rcp(pan+eps);  g = pan*r
// Final: pc = u * r_last.

#define MAXK 128

typedef unsigned long long u64;

__device__ __forceinline__ u64 pack2(float a, float b) {
    u64 r; asm("mov.b64 %0, {%1, %2};" : "=l"(r) : "f"(a), "f"(b)); return r;
}
__device__ __forceinline__ void unpack2(u64 v, float& a, float& b) {
    asm("mov.b64 {%0, %1}, %2;" : "=f"(a), "=f"(b) : "l"(v));
}
__device__ __forceinline__ u64 fma2(u64 a, u64 b, u64 c) {
    u64 d; asm("fma.rn.f32x2 %0, %1, %2, %3;" : "=l"(d) : "l"(a), "l"(b), "l"(c)); return d;
}
__device__ __forceinline__ u64 add2(u64 a, u64 b) {
    u64 d; asm("add.rn.f32x2 %0, %1, %2;" : "=l"(d) : "l"(a), "l"(b)); return d;
}
__device__ __forceinline__ u64 mul2(u64 a, u64 b) {
    u64 d; asm("mul.rn.f32x2 %0, %1, %2;" : "=l"(d) : "l"(a), "l"(b)); return d;
}
__device__ __forceinline__ float ex2f_(float x) {
    float y; asm("ex2.approx.f32 %0, %1;" : "=f"(y) : "f"(x)); return y;
}
__device__ __forceinline__ float rcpf_(float x) {
    float y; asm("rcp.approx.f32 %0, %1;" : "=f"(y) : "f"(x)); return y;
}

struct PairState {
    u64 x, y, x2, xy, y2;   // centered coords + monomials
    u64 u0, u1, u2;         // scaled color numerators
    u64 pa, omp, g, r;      // alpha, 1-alpha, carry factor, last rcp
};

__device__ __forceinline__ void pair_init(PairState& S, float2 P0, float2 P1) {
    float ax = P0.x - 256.0f, ay = P0.y - 256.0f;
    float bx = P1.x - 256.0f, by = P1.y - 256.0f;
    S.x  = pack2(ax, bx);
    S.y  = pack2(ay, by);
    S.x2 = mul2(S.x, S.x);
    S.xy = mul2(S.x, S.y);
    S.y2 = mul2(S.y, S.y);
    S.u0 = S.u1 = S.u2 = 0ull;
    S.pa = 0ull;
    S.g  = 0ull;
    S.r  = 0ull;
    S.omp = pack2(1.0f, 1.0f);
}

__device__ __forceinline__ void pair_step(PairState& S,
                                          ulonglong2 g0, ulonglong2 g1,
                                          ulonglong2 g2, ulonglong2 g3,
                                          ulonglong2 g4,
                                          u64 EPS2, u64 NEG1) {
    u64 t = fma2(g2.x, S.y, g2.y);       // Ey*y + F
    t = fma2(g1.y, S.x, t);              // + Dx*x
    t = fma2(g1.x, S.y2, t);             // + C*y2
    t = fma2(g0.y, S.xy, t);             // + B2*xy
    u64 q = fma2(g0.x, S.x2, t);         // + A*x2

    float qa, qb; unpack2(q, qa, qb);
    u64 e = pack2(ex2f_(qa), ex2f_(qb)); // alpha_k * gaussian

    u64 w   = mul2(e, S.omp);            // contribution weight
    u64 cw0 = mul2(g3.x, w);
    u64 cw1 = mul2(g3.y, w);
    u64 cw2 = mul2(g4.x, w);
    S.u0 = fma2(S.u0, S.g, cw0);         // u = u*g_prev + col*w
    S.u1 = fma2(S.u1, S.g, cw1);
    S.u2 = fma2(S.u2, S.g, cw2);

    u64 pan = add2(S.pa, w);
    S.omp = fma2(w, NEG1, S.omp);
    u64 d = add2(pan, EPS2);
    float da, db; unpack2(d, da, db);
    S.r = pack2(rcpf_(da), rcpf_(db));
    S.g = mul2(pan, S.r);
    S.pa = pan;
}

__device__ __forceinline__ void pair_emit(const PairState& S, float4* out,
                                          int i0, int i1, bool v0, bool v1) {
    float r0, r1;  unpack2(S.r,  r0, r1);
    float a0, a1;  unpack2(S.pa, a0, a1);
    float u00, u01; unpack2(S.u0, u00, u01);
    float u10, u11; unpack2(S.u1, u10, u11);
    float u20, u21; unpack2(S.u2, u20, u21);
    if (v0) {
        out[i0] = make_float4(fminf(fmaxf(u00 * r0, 0.0f), 255.0f),
                              fminf(fmaxf(u10 * r0, 0.0f), 255.0f),
                              fminf(fmaxf(u20 * r0, 0.0f), 255.0f),
                              fminf(fmaxf(a0, 0.0f), 1.0f) * 255.0f);
    }
    if (v1) {
        out[i1] = make_float4(fminf(fmaxf(u01 * r1, 0.0f), 255.0f),
                              fminf(fmaxf(u11 * r1, 0.0f), 255.0f),
                              fminf(fmaxf(u21 * r1, 0.0f), 255.0f),
                              fminf(fmaxf(a1, 0.0f), 1.0f) * 255.0f);
    }
}

template<int KT>
__global__ __launch_bounds__(64)
void gs_splat_kernel(const float* __restrict__ pos,
                     const float* __restrict__ mu,
                     const float* __restrict__ alpha,
                     const float* __restrict__ color,
                     const float* __restrict__ scales,
                     const float* __restrict__ thetas,
                     float4* __restrict__ out,
                     int n, int K)
{
    const int KK = (KT > 0) ? KT : MAXK;
    // per-k: 10 broadcast f32x2 pairs (80 B) -> 5x LDS.128 per k
    __shared__ __align__(16) float2 sp[MAXK * 10];

    const float L2E = 1.44269504088896340736f;

    // ---- per-CTA param prep (blockDim=64 -> each thread preps <=2 k) ----
    for (int k = threadIdx.x; k < K; k += blockDim.x) {
        float th = thetas[k];
        float c = cosf(th), s = sinf(th);
        float sx = fmaxf(scales[2 * k + 0], 0.1f);
        float sy = fmaxf(scales[2 * k + 1], 0.1f);
        float ix = 1.0f / (sx * sx);
        float iy = 1.0f / (sy * sy);
        float S00 = c * c * ix + s * s * iy;
        float S01 = c * s * (ix - iy);
        float S11 = s * s * ix + c * c * iy;
        float h = -0.5f * L2E;
        float A  = h * S00;
        float B2 = (2.0f * h) * S01;
        float C  = h * S11;
        float a  = fminf(fmaxf(alpha[k], 0.0f), 1.0f);
        float la = log2f(fmaxf(a, 1e-38f));
        float c0 = fminf(fmaxf(color[3 * k + 0], 0.0f), 255.0f);
        float c1 = fminf(fmaxf(color[3 * k + 1], 0.0f), 255.0f);
        float c2 = fminf(fmaxf(color[3 * k + 2], 0.0f), 255.0f);
        float mx = mu[2 * k + 0] - 256.0f;   // centered
        float my = mu[2 * k + 1] - 256.0f;
        float Dx = -(2.0f * A * mx + B2 * my);
        float Ey = -(B2 * mx + 2.0f * C * my);
        float F  = (A * mx * mx + B2 * mx * my + C * my * my) + la;
        float2* p = &sp[k * 10];
        p[0] = make_float2(A, A);
        p[1] = make_float2(B2, B2);
        p[2] = make_float2(C, C);
        p[3] = make_float2(Dx, Dx);
        p[4] = make_float2(Ey, Ey);
        p[5] = make_float2(F, F);
        p[6] = make_float2(c0, c0);
        p[7] = make_float2(c1, c1);
        p[8] = make_float2(c2, c2);
        p[9] = make_float2(0.0f, 0.0f);
    }
    __syncthreads();

    // ---- 4 pixels per thread (2 packed pairs), coalesced within block ----
    int base = blockIdx.x * ((int)blockDim.x * 4);
    int i0 = base + threadIdx.x;
    int i1 = i0 + blockDim.x;
    int i2 = i0 + 2 * blockDim.x;
    int i3 = i0 + 3 * blockDim.x;
    bool v0 = (i0 < n), v1 = (i1 < n), v2 = (i2 < n), v3 = (i3 < n);
    const float2* pos2 = (const float2*)pos;
    float2 P0 = v0 ? pos2[i0] : make_float2(0.0f, 0.0f);
    float2 P1 = v1 ? pos2[i1] : make_float2(0.0f, 0.0f);
    float2 P2 = v2 ? pos2[i2] : make_float2(0.0f, 0.0f);
    float2 P3 = v3 ? pos2[i3] : make_float2(0.0f, 0.0f);

    PairState Sa, Sb;
    pair_init(Sa, P0, P1);
    pair_init(Sb, P2, P3);

    const u64 EPS2 = pack2(1e-8f, 1e-8f);
    const u64 NEG1 = pack2(-1.0f, -1.0f);
    const ulonglong2* __restrict__ g = (const ulonglong2*)sp;

#pragma unroll 8
    for (int k = 0; k < KK; k++) {
        ulonglong2 g0 = g[k * 5 + 0];   // {A2,  B22}
        ulonglong2 g1 = g[k * 5 + 1];   // {C2,  Dx2}
        ulonglong2 g2 = g[k * 5 + 2];   // {Ey2, F2}
        ulonglong2 g3 = g[k * 5 + 3];   // {c02, c12}
        ulonglong2 g4 = g[k * 5 + 4];   // {c22, pad}
        pair_step(Sa, g0, g1, g2, g3, g4, EPS2, NEG1);
        pair_step(Sb, g0, g1, g2, g3, g4, EPS2, NEG1);
    }

    pair_emit(Sa, out, i0, i1, v0, v1);
    pair_emit(Sb, out, i2, i3, v2, v3);
}

extern "C" void kernel_launch(void* const* d_in, const int* in_sizes, int n_in,
                              void* d_out, int out_size)
{
    const float* pos    = (const float*)d_in[0];
    const float* mu     = (const float*)d_in[1];
    const float* alpha  = (const float*)d_in[2];
    const float* color  = (const float*)d_in[3];
    const float* scales = (const float*)d_in[4];
    const float* thetas = (const float*)d_in[5];

    int n = in_sizes[0] / 2;     // pixels
    int K = in_sizes[2];         // gaussians
    if (K > MAXK) K = MAXK;

    const int threads = 64;
    const int pixPerCta = threads * 4;   // 256 pixels per block
    int grid = (n + pixPerCta - 1) / pixPerCta;

    if (K == 128) {
        gs_splat_kernel<128><<<grid, threads>>>(pos, mu, alpha, color, scales,
                                                thetas, (float4*)d_out, n, K);
    } else {
        gs_splat_kernel<0><<<grid, threads>>>(pos, mu, alpha, color, scales,
                                              thetas, (float4*)d_out, n, K);
    }
}

// round 10
// speedup vs baseline: 3.3005x; 1.0539x over previous
#include <cuda_runtime.h>

// Gaussian-splat over-compositing, N pixels x K gaussians, sm_103a.
// R10: dense exact loop (R3 math, passed @2.5e-6), ONE packed pair-state per
// thread (2 px), 64-thread blocks, grid 2048 (~14 blocks/SM, occ ~43%) to
// cover MUFU/FFMA2 latency; fewer live b64 pairs -> fewer forced MOVs.
//   e   = exp2(A*x2 + B2*xy + C*y2 + Dx*x + Ey*y + F)
//   w   = e * omp;  u_c = u_c * g_prev + col_c * w
//   pan = pa + w;  omp -= w;  r = rcp(pan+eps);  g = pan*r
// Final: pc = u * r_last.

#define MAXK 128

typedef unsigned long long u64;

__device__ __forceinline__ u64 pack2(float a, float b) {
    u64 r; asm("mov.b64 %0, {%1, %2};" : "=l"(r) : "f"(a), "f"(b)); return r;
}
__device__ __forceinline__ void unpack2(u64 v, float& a, float& b) {
    asm("mov.b64 {%0, %1}, %2;" : "=f"(a), "=f"(b) : "l"(v));
}
__device__ __forceinline__ u64 fma2(u64 a, u64 b, u64 c) {
    u64 d; asm("fma.rn.f32x2 %0, %1, %2, %3;" : "=l"(d) : "l"(a), "l"(b), "l"(c)); return d;
}
__device__ __forceinline__ u64 add2(u64 a, u64 b) {
    u64 d; asm("add.rn.f32x2 %0, %1, %2;" : "=l"(d) : "l"(a), "l"(b)); return d;
}
__device__ __forceinline__ u64 mul2(u64 a, u64 b) {
    u64 d; asm("mul.rn.f32x2 %0, %1, %2;" : "=l"(d) : "l"(a), "l"(b)); return d;
}
__device__ __forceinline__ float ex2f_(float x) {
    float y; asm("ex2.approx.f32 %0, %1;" : "=f"(y) : "f"(x)); return y;
}
__device__ __forceinline__ float rcpf_(float x) {
    float y; asm("rcp.approx.f32 %0, %1;" : "=f"(y) : "f"(x)); return y;
}

template<int KT>
__global__ __launch_bounds__(64)
void gs_splat_kernel(const float* __restrict__ pos,
                     const float* __restrict__ mu,
                     const float* __restrict__ alpha,
                     const float* __restrict__ color,
                     const float* __restrict__ scales,
                     const float* __restrict__ thetas,
                     float4* __restrict__ out,
                     int n, int K)
{
    const int KK = (KT > 0) ? KT : MAXK;
    // per-k: 10 broadcast f32x2 pairs (80 B) -> 5x LDS.128 per k
    __shared__ __align__(16) float2 sp[MAXK * 10];

    const float L2E = 1.44269504088896340736f;

    // ---- per-CTA param prep (blockDim=64 -> each thread preps <=2 k) ----
    for (int k = threadIdx.x; k < K; k += blockDim.x) {
        float th = thetas[k];
        float c = cosf(th), s = sinf(th);
        float sx = fmaxf(scales[2 * k + 0], 0.1f);
        float sy = fmaxf(scales[2 * k + 1], 0.1f);
        float ix = 1.0f / (sx * sx);
        float iy = 1.0f / (sy * sy);
        float S00 = c * c * ix + s * s * iy;
        float S01 = c * s * (ix - iy);
        float S11 = s * s * ix + c * c * iy;
        float h = -0.5f * L2E;
        float A  = h * S00;
        float B2 = (2.0f * h) * S01;
        float C  = h * S11;
        float a  = fminf(fmaxf(alpha[k], 0.0f), 1.0f);
        float la = log2f(fmaxf(a, 1e-38f));
        float c0 = fminf(fmaxf(color[3 * k + 0], 0.0f), 255.0f);
        float c1 = fminf(fmaxf(color[3 * k + 1], 0.0f), 255.0f);
        float c2 = fminf(fmaxf(color[3 * k + 2], 0.0f), 255.0f);
        float mx = mu[2 * k + 0] - 256.0f;   // centered
        float my = mu[2 * k + 1] - 256.0f;
        float Dx = -(2.0f * A * mx + B2 * my);
        float Ey = -(B2 * mx + 2.0f * C * my);
        float F  = (A * mx * mx + B2 * mx * my + C * my * my) + la;
        float2* p = &sp[k * 10];
        p[0] = make_float2(A, A);
        p[1] = make_float2(B2, B2);
        p[2] = make_float2(C, C);
        p[3] = make_float2(Dx, Dx);
        p[4] = make_float2(Ey, Ey);
        p[5] = make_float2(F, F);
        p[6] = make_float2(c0, c0);
        p[7] = make_float2(c1, c1);
        p[8] = make_float2(c2, c2);
        p[9] = make_float2(0.0f, 0.0f);
    }
    __syncthreads();

    // ---- 2 pixels per thread (ONE packed pair), coalesced within block ----
    int base = blockIdx.x * ((int)blockDim.x * 2);
    int i0 = base + threadIdx.x;
    int i1 = i0 + blockDim.x;
    bool v0 = (i0 < n), v1 = (i1 < n);
    const float2* pos2 = (const float2*)pos;
    float2 P0 = v0 ? pos2[i0] : make_float2(0.0f, 0.0f);
    float2 P1 = v1 ? pos2[i1] : make_float2(0.0f, 0.0f);

    float ax = P0.x - 256.0f, ay = P0.y - 256.0f;
    float bx = P1.x - 256.0f, by = P1.y - 256.0f;
    u64 X  = pack2(ax, bx);
    u64 Y  = pack2(ay, by);
    u64 X2 = mul2(X, X);
    u64 XY = mul2(X, Y);
    u64 Y2 = mul2(Y, Y);

    u64 u0 = 0ull, u1 = 0ull, u2 = 0ull;   // scaled color numerators
    u64 pa = 0ull;                          // accumulated alpha
    u64 gC = 0ull;                          // carry factor pa/(pa+eps)
    u64 rC = 0ull;                          // last rcp
    u64 omp = pack2(1.0f, 1.0f);            // 1 - pa
    const u64 EPS2 = pack2(1e-8f, 1e-8f);
    const u64 NEG1 = pack2(-1.0f, -1.0f);

    const ulonglong2* __restrict__ g = (const ulonglong2*)sp;

#pragma unroll 8
    for (int k = 0; k < KK; k++) {
        ulonglong2 g0 = g[k * 5 + 0];   // {A2,  B22}
        ulonglong2 g1 = g[k * 5 + 1];   // {C2,  Dx2}
        ulonglong2 g2 = g[k * 5 + 2];   // {Ey2, F2}
        ulonglong2 g3 = g[k * 5 + 3];   // {c02, c12}
        ulonglong2 g4 = g[k * 5 + 4];   // {c22, pad}

        u64 t = fma2(g2.x, Y, g2.y);        // Ey*y + F
        t = fma2(g1.y, X, t);               // + Dx*x
        t = fma2(g1.x, Y2, t);              // + C*y2
        t = fma2(g0.y, XY, t);              // + B2*xy
        u64 q = fma2(g0.x, X2, t);          // + A*x2

        float qa, qb; unpack2(q, qa, qb);
        u64 e = pack2(ex2f_(qa), ex2f_(qb)); // alpha_k * gaussian

        u64 w   = mul2(e, omp);              // contribution weight
        u64 cw0 = mul2(g3.x, w);
        u64 cw1 = mul2(g3.y, w);
        u64 cw2 = mul2(g4.x, w);
        u0 = fma2(u0, gC, cw0);              // u = u*g_prev + col*w
        u1 = fma2(u1, gC, cw1);
        u2 = fma2(u2, gC, cw2);

        u64 pan = add2(pa, w);
        omp = fma2(w, NEG1, omp);
        u64 d = add2(pan, EPS2);
        float da, db; unpack2(d, da, db);
        rC = pack2(rcpf_(da), rcpf_(db));
        gC = mul2(pan, rC);
        pa = pan;
    }

    float r0, r1;  unpack2(rC, r0, r1);
    float a0, a1;  unpack2(pa, a0, a1);
    float u00, u01; unpack2(u0, u00, u01);
    float u10, u11; unpack2(u1, u10, u11);
    float u20, u21; unpack2(u2, u20, u21);

    if (v0) {
        out[i0] = make_float4(fminf(fmaxf(u00 * r0, 0.0f), 255.0f),
                              fminf(fmaxf(u10 * r0, 0.0f), 255.0f),
                              fminf(fmaxf(u20 * r0, 0.0f), 255.0f),
                              fminf(fmaxf(a0, 0.0f), 1.0f) * 255.0f);
    }
    if (v1) {
        out[i1] = make_float4(fminf(fmaxf(u01 * r1, 0.0f), 255.0f),
                              fminf(fmaxf(u11 * r1, 0.0f), 255.0f),
                              fminf(fmaxf(u21 * r1, 0.0f), 255.0f),
                              fminf(fmaxf(a1, 0.0f), 1.0f) * 255.0f);
    }
}

extern "C" void kernel_launch(void* const* d_in, const int* in_sizes, int n_in,
                              void* d_out, int out_size)
{
    const float* pos    = (const float*)d_in[0];
    const float* mu     = (const float*)d_in[1];
    const float* alpha  = (const float*)d_in[2];
    const float* color  = (const float*)d_in[3];
    const float* scales = (const float*)d_in[4];
    const float* thetas = (const float*)d_in[5];

    int n = in_sizes[0] / 2;     // pixels
    int K = in_sizes[2];         // gaussians
    if (K > MAXK) K = MAXK;

    const int threads = 64;
    const int pixPerCta = threads * 2;   // 128 pixels per block
    int grid = (n + pixPerCta - 1) / pixPerCta;

    if (K == 128) {
        gs_splat_kernel<128><<<grid, threads>>>(pos, mu, alpha, color, scales,
                                                thetas, (float4*)d_out, n, K);
    } else {
        gs_splat_kernel<0><<<grid, threads>>>(pos, mu, alpha, color, scales,
                                              thetas, (float4*)d_out, n, K);
    }
}